// round 11
// baseline (speedup 1.0000x reference)
#include <cuda_runtime.h>

// Problem dims (fixed by setup_inputs): N1=N2=256 -> N=512, F=512, H=512, R=4
#define NT   512           // total rows of x
#define FD   512           // feature dim
#define HD   512           // hidden dim
#define RD   4             // relations
#define NH   (NT*HD)       // 262144

// ---------------- scratch (no allocations allowed) ----------------
__device__ float g_X  [NT*FD];        // concat(x)                1 MB
__device__ float g_A  [RD*NT*HD];     // a'[r][i][h] = x@Wl^T+b1  4 MB
__device__ float g_B  [RD*NT*HD];     // b [r][j][h] = x@Wr^T     4 MB
__device__ float g_S  [RD*NT*NT];     // scores per relation      4 MB
__device__ float g_sa [RD*NT];        // row sums of A'
__device__ float g_saa[RD*NT];        // row sumsq of A'
__device__ float g_sb [RD*NT];
__device__ float g_sbb[RD*NT];

// ---------------- 1) concat: x = [img; txt], also output #0 ----------------
__global__ void concat_kernel(const float4* __restrict__ img,
                              const float4* __restrict__ txt,
                              float4* __restrict__ out_x) {
    int idx = blockIdx.x * blockDim.x + threadIdx.x;   // 65536 float4
    float4 v = (idx < 256 * (FD/4)) ? img[idx] : txt[idx - 256 * (FD/4)];
    ((float4*)g_X)[idx] = v;
    out_x[idx] = v;
}

// ---------------- 2) SGEMM: A'/B = X @ W^T (+b1 for A') ----------------
// blockIdx.z = rh in [0,8): r = rh>>1, half = rh&1 (0 -> Wl -> A', 1 -> Wr -> B)
// 64x64 output tile, BK=16, 256 threads, 4x4 micro-tile.
__global__ __launch_bounds__(256) void gemm_kernel(const float* __restrict__ W1,
                                                   const float* __restrict__ b1) {
    const int rh = blockIdx.z;
    const int r = rh >> 1, half = rh & 1;
    const int i0 = blockIdx.y * 64, h0 = blockIdx.x * 64;

    __shared__ float Xs[64][17];
    __shared__ float Ws[64][17];

    const int t   = threadIdx.x;
    const int row = t >> 2, col4 = (t & 3) * 4;   // loader: 64 rows x 4 float4
    const int ty  = t >> 4, tx = t & 15;          // compute: 16x16 threads
    const int iy  = ty * 4, jx = tx * 4;

    const float* __restrict__ Wbase = W1 + (size_t)(r * HD + h0) * (2 * FD) + half * FD;

    float acc[4][4];
#pragma unroll
    for (int u = 0; u < 4; u++)
#pragma unroll
        for (int v = 0; v < 4; v++) acc[u][v] = 0.f;

    for (int k0 = 0; k0 < FD; k0 += 16) {
        float4 xv = *(const float4*)&g_X[(i0 + row) * FD + k0 + col4];
        float4 wv = *(const float4*)&Wbase[(size_t)row * (2 * FD) + k0 + col4];
        Xs[row][col4 + 0] = xv.x; Xs[row][col4 + 1] = xv.y;
        Xs[row][col4 + 2] = xv.z; Xs[row][col4 + 3] = xv.w;
        Ws[row][col4 + 0] = wv.x; Ws[row][col4 + 1] = wv.y;
        Ws[row][col4 + 2] = wv.z; Ws[row][col4 + 3] = wv.w;
        __syncthreads();
#pragma unroll
        for (int k = 0; k < 16; k++) {
            float a[4], b[4];
#pragma unroll
            for (int u = 0; u < 4; u++) a[u] = Xs[iy + u][k];
#pragma unroll
            for (int v = 0; v < 4; v++) b[v] = Ws[jx + v][k];
#pragma unroll
            for (int u = 0; u < 4; u++)
#pragma unroll
                for (int v = 0; v < 4; v++) acc[u][v] = fmaf(a[u], b[v], acc[u][v]);
        }
        __syncthreads();
    }

    float* __restrict__ out = (half ? g_B : g_A) + (size_t)r * NT * HD;
    float bias[4] = {0.f, 0.f, 0.f, 0.f};
    if (!half) {
#pragma unroll
        for (int v = 0; v < 4; v++) bias[v] = b1[r * HD + h0 + jx + v];
    }
#pragma unroll
    for (int u = 0; u < 4; u++) {
        float4 o;
        o.x = acc[u][0] + bias[0];
        o.y = acc[u][1] + bias[1];
        o.z = acc[u][2] + bias[2];
        o.w = acc[u][3] + bias[3];
        *(float4*)&out[(size_t)(i0 + iy + u) * HD + h0 + jx] = o;
    }
}

// ---------------- 3) row stats: sum & sumsq over H for A' and B ----------------
// one warp per (buf, r, row); 8 warps/block -> 512 blocks
__global__ void rowstats_kernel() {
    int gwarp = blockIdx.x * 8 + (threadIdx.x >> 5);   // 0..4095
    int lane  = threadIdx.x & 31;
    int buf   = gwarp >> 11;        // 0: A, 1: B
    int rrow  = gwarp & 2047;       // r*512 + row
    const float* __restrict__ src = (buf ? g_B : g_A) + (size_t)rrow * HD;
    float s = 0.f, ss = 0.f;
#pragma unroll
    for (int k = lane; k < HD; k += 32) {
        float v = src[k];
        s += v;
        ss = fmaf(v, v, ss);
    }
#pragma unroll
    for (int o = 16; o > 0; o >>= 1) {
        s  += __shfl_xor_sync(0xffffffffu, s,  o);
        ss += __shfl_xor_sync(0xffffffffu, ss, o);
    }
    if (lane == 0) {
        if (buf) { g_sb[rrow] = s; g_sbb[rrow] = ss; }
        else     { g_sa[rrow] = s; g_saa[rrow] = ss; }
    }
}

// ---------------- 4) pair kernel: cross-dot -> LN stats -> relu-dot ----------------
// grid (8, 8, 4): 64x64 pair tile per block for relation r = blockIdx.z
// 256 threads, 4x4 micro-tile, BK=32, two sweeps over H (data L2-resident).
__global__ __launch_bounds__(256) void pair_kernel(const float* __restrict__ gamma,
                                                   const float* __restrict__ beta,
                                                   const float* __restrict__ w2,
                                                   const float* __restrict__ b2) {
    const int r  = blockIdx.z;
    const int i0 = blockIdx.y * 64, j0 = blockIdx.x * 64;

    __shared__ float As[64][33];
    __shared__ float Bs[64][33];
    __shared__ float gs[32], bes[32], ws[32];

    const int t  = threadIdx.x;
    const int ty = t >> 4, tx = t & 15;
    const int iy = ty * 4, jx = tx * 4;

    const float* __restrict__ Ab = g_A + (size_t)r * NT * HD + (size_t)i0 * HD;
    const float* __restrict__ Bb = g_B + (size_t)r * NT * HD + (size_t)j0 * HD;

    // ---- phase 1: cross[u][v] = a'_i . b_j ----
    float cross[4][4];
#pragma unroll
    for (int u = 0; u < 4; u++)
#pragma unroll
        for (int v = 0; v < 4; v++) cross[u][v] = 0.f;

    for (int k0 = 0; k0 < HD; k0 += 32) {
#pragma unroll
        for (int p = 0; p < 2; p++) {
            int id = t + p * 256;
            int rw = id >> 3, c4 = (id & 7) * 4;
            float4 av = *(const float4*)&Ab[(size_t)rw * HD + k0 + c4];
            float4 bv = *(const float4*)&Bb[(size_t)rw * HD + k0 + c4];
            As[rw][c4 + 0] = av.x; As[rw][c4 + 1] = av.y;
            As[rw][c4 + 2] = av.z; As[rw][c4 + 3] = av.w;
            Bs[rw][c4 + 0] = bv.x; Bs[rw][c4 + 1] = bv.y;
            Bs[rw][c4 + 2] = bv.z; Bs[rw][c4 + 3] = bv.w;
        }
        __syncthreads();
#pragma unroll
        for (int k = 0; k < 32; k++) {
            float a[4], b[4];
#pragma unroll
            for (int u = 0; u < 4; u++) a[u] = As[iy + u][k];
#pragma unroll
            for (int v = 0; v < 4; v++) b[v] = Bs[jx + v][k];
#pragma unroll
            for (int u = 0; u < 4; u++)
#pragma unroll
                for (int v = 0; v < 4; v++) cross[u][v] = fmaf(a[u], b[v], cross[u][v]);
        }
        __syncthreads();
    }

    // ---- per-pair LN stats: q = rstd, m = mu*rstd ----
    float q[4][4], m[4][4];
    {
        float sa_[4], saa_[4], sb_[4], sbb_[4];
#pragma unroll
        for (int u = 0; u < 4; u++) {
            sa_[u]  = g_sa [r * NT + i0 + iy + u];
            saa_[u] = g_saa[r * NT + i0 + iy + u];
        }
#pragma unroll
        for (int v = 0; v < 4; v++) {
            sb_[v]  = g_sb [r * NT + j0 + jx + v];
            sbb_[v] = g_sbb[r * NT + j0 + jx + v];
        }
        const float invH = 1.0f / (float)HD;
#pragma unroll
        for (int u = 0; u < 4; u++)
#pragma unroll
            for (int v = 0; v < 4; v++) {
                float mu  = (sa_[u] + sb_[v]) * invH;
                float e2  = (saa_[u] + sbb_[v] + 2.0f * cross[u][v]) * invH;
                float var = e2 - mu * mu;
                float rstd = rsqrtf(var + 1e-5f);
                q[u][v] = rstd;
                m[u][v] = mu * rstd;
            }
    }

    // ---- phase 2: s = sum_h relu((p - mu)*rstd*gamma + beta) * w2 ----
    float s[4][4];
#pragma unroll
    for (int u = 0; u < 4; u++)
#pragma unroll
        for (int v = 0; v < 4; v++) s[u][v] = 0.f;

    for (int k0 = 0; k0 < HD; k0 += 32) {
#pragma unroll
        for (int p = 0; p < 2; p++) {
            int id = t + p * 256;
            int rw = id >> 3, c4 = (id & 7) * 4;
            float4 av = *(const float4*)&Ab[(size_t)rw * HD + k0 + c4];
            float4 bv = *(const float4*)&Bb[(size_t)rw * HD + k0 + c4];
            As[rw][c4 + 0] = av.x; As[rw][c4 + 1] = av.y;
            As[rw][c4 + 2] = av.z; As[rw][c4 + 3] = av.w;
            Bs[rw][c4 + 0] = bv.x; Bs[rw][c4 + 1] = bv.y;
            Bs[rw][c4 + 2] = bv.z; Bs[rw][c4 + 3] = bv.w;
        }
        if (t < 32) {
            gs [t] = gamma[r * HD + k0 + t];
            bes[t] = beta [r * HD + k0 + t];
            ws [t] = w2   [r * HD + k0 + t];
        }
        __syncthreads();
#pragma unroll
        for (int k = 0; k < 32; k++) {
            float g = gs[k], be = bes[k], w = ws[k];
            float a[4], b[4];
#pragma unroll
            for (int u = 0; u < 4; u++) a[u] = As[iy + u][k];
#pragma unroll
            for (int v = 0; v < 4; v++) b[v] = Bs[jx + v][k];
#pragma unroll
            for (int u = 0; u < 4; u++)
#pragma unroll
                for (int v = 0; v < 4; v++) {
                    float pz = a[u] + b[v];
                    float z  = fmaf(pz, q[u][v], -m[u][v]);   // (p - mu)*rstd
                    float tv = fmaf(z, g, be);
                    tv = fmaxf(tv, 0.0f);
                    s[u][v] = fmaf(tv, w, s[u][v]);
                }
        }
        __syncthreads();
    }

    const float bb = b2[r];
    float* __restrict__ Sout = g_S + (size_t)r * NT * NT;
#pragma unroll
    for (int u = 0; u < 4; u++) {
        float4 o;
        o.x = s[u][0] + bb;
        o.y = s[u][1] + bb;
        o.z = s[u][2] + bb;
        o.w = s[u][3] + bb;
        *(float4*)&Sout[(size_t)(i0 + iy + u) * NT + j0 + jx] = o;
    }
}

// ---------------- 5) finalize: max/argmax over r, threshold mask ----------------
// out layout: [x (262144)][best_score (262144)][best_rel (262144)][edge_mask (262144)]
__global__ void finalize_kernel(float* __restrict__ out) {
    int idx = blockIdx.x * blockDim.x + threadIdx.x;   // 262144
    float s0 = g_S[idx];
    float s1 = g_S[NT * NT + idx];
    float s2 = g_S[2 * NT * NT + idx];
    float s3 = g_S[3 * NT * NT + idx];
    float best = s0; int rel = 0;
    if (s1 > best) { best = s1; rel = 1; }
    if (s2 > best) { best = s2; rel = 2; }
    if (s3 > best) { best = s3; rel = 3; }
    int i = idx >> 9, j = idx & (NT - 1);
    out[NT * NT     + idx] = best;
    out[2 * NT * NT + idx] = (float)rel;
    out[3 * NT * NT + idx] = (i != j && best > 0.2f) ? 1.0f : 0.0f;
}

// ---------------- launch ----------------
extern "C" void kernel_launch(void* const* d_in, const int* in_sizes, int n_in,
                              void* d_out, int out_size) {
    (void)in_sizes; (void)n_in; (void)out_size;
    const float* img   = (const float*)d_in[0];
    const float* txt   = (const float*)d_in[1];
    const float* W1    = (const float*)d_in[2];
    const float* b1    = (const float*)d_in[3];
    const float* gamma = (const float*)d_in[4];
    const float* beta  = (const float*)d_in[5];
    const float* w2    = (const float*)d_in[6];
    const float* b2    = (const float*)d_in[7];
    float* out = (float*)d_out;

    concat_kernel<<<256, 256>>>((const float4*)img, (const float4*)txt, (float4*)out);

    dim3 gg(8, 8, 8);                 // (h tiles, i tiles, r*2+half)
    gemm_kernel<<<gg, 256>>>(W1, b1);

    rowstats_kernel<<<512, 256>>>();

    dim3 pg(8, 8, 4);                 // (j tiles, i tiles, r)
    pair_kernel<<<pg, 256>>>(gamma, beta, w2, b2);

    finalize_kernel<<<1024, 256>>>(out);
}

// round 12
// speedup vs baseline: 1.0010x; 1.0010x over previous
#include <cuda_runtime.h>

// Problem dims (fixed by setup_inputs): N1=N2=256 -> N=512, F=512, H=512, R=4
#define NT   512           // total rows of x
#define FD   512           // feature dim
#define HD   512           // hidden dim
#define RD   4             // relations
#define NH   (NT*HD)       // 262144

// ---------------- scratch (no allocations allowed) ----------------
__device__ float g_X  [NT*FD];        // concat(x)                1 MB
__device__ float g_A  [RD*NT*HD];     // a'[r][i][h] = x@Wl^T+b1  4 MB
__device__ float g_B  [RD*NT*HD];     // b [r][j][h] = x@Wr^T     4 MB
__device__ float g_S  [RD*NT*NT];     // scores per relation      4 MB
__device__ float g_sa [RD*NT];        // row sums of A'
__device__ float g_saa[RD*NT];        // row sumsq of A'
__device__ float g_sb [RD*NT];
__device__ float g_sbb[RD*NT];

// ---------------- 1) concat: x = [img; txt], also output #0 ----------------
__global__ void concat_kernel(const float4* __restrict__ img,
                              const float4* __restrict__ txt,
                              float4* __restrict__ out_x) {
    int idx = blockIdx.x * blockDim.x + threadIdx.x;   // 65536 float4
    float4 v = (idx < 256 * (FD/4)) ? img[idx] : txt[idx - 256 * (FD/4)];
    ((float4*)g_X)[idx] = v;
    out_x[idx] = v;
}

// ---------------- 2) SGEMM: A'/B = X @ W^T (+b1 for A') ----------------
// blockIdx.z = rh in [0,8): r = rh>>1, half = rh&1 (0 -> Wl -> A', 1 -> Wr -> B)
// 64x64 output tile, BK=16, 256 threads, 4x4 micro-tile.
__global__ __launch_bounds__(256) void gemm_kernel(const float* __restrict__ W1,
                                                   const float* __restrict__ b1) {
    const int rh = blockIdx.z;
    const int r = rh >> 1, half = rh & 1;
    const int i0 = blockIdx.y * 64, h0 = blockIdx.x * 64;

    __shared__ float Xs[64][17];
    __shared__ float Ws[64][17];

    const int t   = threadIdx.x;
    const int row = t >> 2, col4 = (t & 3) * 4;   // loader: 64 rows x 4 float4
    const int ty  = t >> 4, tx = t & 15;          // compute: 16x16 threads
    const int iy  = ty * 4, jx = tx * 4;

    const float* __restrict__ Wbase = W1 + (size_t)(r * HD + h0) * (2 * FD) + half * FD;

    float acc[4][4];
#pragma unroll
    for (int u = 0; u < 4; u++)
#pragma unroll
        for (int v = 0; v < 4; v++) acc[u][v] = 0.f;

    for (int k0 = 0; k0 < FD; k0 += 16) {
        float4 xv = *(const float4*)&g_X[(i0 + row) * FD + k0 + col4];
        float4 wv = *(const float4*)&Wbase[(size_t)row * (2 * FD) + k0 + col4];
        Xs[row][col4 + 0] = xv.x; Xs[row][col4 + 1] = xv.y;
        Xs[row][col4 + 2] = xv.z; Xs[row][col4 + 3] = xv.w;
        Ws[row][col4 + 0] = wv.x; Ws[row][col4 + 1] = wv.y;
        Ws[row][col4 + 2] = wv.z; Ws[row][col4 + 3] = wv.w;
        __syncthreads();
#pragma unroll
        for (int k = 0; k < 16; k++) {
            float a[4], b[4];
#pragma unroll
            for (int u = 0; u < 4; u++) a[u] = Xs[iy + u][k];
#pragma unroll
            for (int v = 0; v < 4; v++) b[v] = Ws[jx + v][k];
#pragma unroll
            for (int u = 0; u < 4; u++)
#pragma unroll
                for (int v = 0; v < 4; v++) acc[u][v] = fmaf(a[u], b[v], acc[u][v]);
        }
        __syncthreads();
    }

    float* __restrict__ out = (half ? g_B : g_A) + (size_t)r * NT * HD;
    float bias[4] = {0.f, 0.f, 0.f, 0.f};
    if (!half) {
#pragma unroll
        for (int v = 0; v < 4; v++) bias[v] = b1[r * HD + h0 + jx + v];
    }
#pragma unroll
    for (int u = 0; u < 4; u++) {
        float4 o;
        o.x = acc[u][0] + bias[0];
        o.y = acc[u][1] + bias[1];
        o.z = acc[u][2] + bias[2];
        o.w = acc[u][3] + bias[3];
        *(float4*)&out[(size_t)(i0 + iy + u) * HD + h0 + jx] = o;
    }
}

// ---------------- 3) row stats: sum & sumsq over H for A' and B ----------------
// one warp per (buf, r, row); 8 warps/block -> 512 blocks
__global__ void rowstats_kernel() {
    int gwarp = blockIdx.x * 8 + (threadIdx.x >> 5);   // 0..4095
    int lane  = threadIdx.x & 31;
    int buf   = gwarp >> 11;        // 0: A, 1: B
    int rrow  = gwarp & 2047;       // r*512 + row
    const float* __restrict__ src = (buf ? g_B : g_A) + (size_t)rrow * HD;
    float s = 0.f, ss = 0.f;
#pragma unroll
    for (int k = lane; k < HD; k += 32) {
        float v = src[k];
        s += v;
        ss = fmaf(v, v, ss);
    }
#pragma unroll
    for (int o = 16; o > 0; o >>= 1) {
        s  += __shfl_xor_sync(0xffffffffu, s,  o);
        ss += __shfl_xor_sync(0xffffffffu, ss, o);
    }
    if (lane == 0) {
        if (buf) { g_sb[rrow] = s; g_sbb[rrow] = ss; }
        else     { g_sa[rrow] = s; g_saa[rrow] = ss; }
    }
}

// ---------------- 4) pair kernel: cross-dot -> LN stats -> relu-dot ----------------
// grid (8, 8, 4): 64x64 pair tile per block for relation r = blockIdx.z
// 256 threads, 4x4 micro-tile, BK=32, two sweeps over H (data L2-resident).
__global__ __launch_bounds__(256) void pair_kernel(const float* __restrict__ gamma,
                                                   const float* __restrict__ beta,
                                                   const float* __restrict__ w2,
                                                   const float* __restrict__ b2) {
    const int r  = blockIdx.z;
    const int i0 = blockIdx.y * 64, j0 = blockIdx.x * 64;

    __shared__ float As[64][33];
    __shared__ float Bs[64][33];
    __shared__ float gs[32], bes[32], ws[32];

    const int t  = threadIdx.x;
    const int ty = t >> 4, tx = t & 15;
    const int iy = ty * 4, jx = tx * 4;

    const float* __restrict__ Ab = g_A + (size_t)r * NT * HD + (size_t)i0 * HD;
    const float* __restrict__ Bb = g_B + (size_t)r * NT * HD + (size_t)j0 * HD;

    // ---- phase 1: cross[u][v] = a'_i . b_j ----
    float cross[4][4];
#pragma unroll
    for (int u = 0; u < 4; u++)
#pragma unroll
        for (int v = 0; v < 4; v++) cross[u][v] = 0.f;

    for (int k0 = 0; k0 < HD; k0 += 32) {
#pragma unroll
        for (int p = 0; p < 2; p++) {
            int id = t + p * 256;
            int rw = id >> 3, c4 = (id & 7) * 4;
            float4 av = *(const float4*)&Ab[(size_t)rw * HD + k0 + c4];
            float4 bv = *(const float4*)&Bb[(size_t)rw * HD + k0 + c4];
            As[rw][c4 + 0] = av.x; As[rw][c4 + 1] = av.y;
            As[rw][c4 + 2] = av.z; As[rw][c4 + 3] = av.w;
            Bs[rw][c4 + 0] = bv.x; Bs[rw][c4 + 1] = bv.y;
            Bs[rw][c4 + 2] = bv.z; Bs[rw][c4 + 3] = bv.w;
        }
        __syncthreads();
#pragma unroll
        for (int k = 0; k < 32; k++) {
            float a[4], b[4];
#pragma unroll
            for (int u = 0; u < 4; u++) a[u] = As[iy + u][k];
#pragma unroll
            for (int v = 0; v < 4; v++) b[v] = Bs[jx + v][k];
#pragma unroll
            for (int u = 0; u < 4; u++)
#pragma unroll
                for (int v = 0; v < 4; v++) cross[u][v] = fmaf(a[u], b[v], cross[u][v]);
        }
        __syncthreads();
    }

    // ---- per-pair LN stats: q = rstd, m = mu*rstd ----
    float q[4][4], m[4][4];
    {
        float sa_[4], saa_[4], sb_[4], sbb_[4];
#pragma unroll
        for (int u = 0; u < 4; u++) {
            sa_[u]  = g_sa [r * NT + i0 + iy + u];
            saa_[u] = g_saa[r * NT + i0 + iy + u];
        }
#pragma unroll
        for (int v = 0; v < 4; v++) {
            sb_[v]  = g_sb [r * NT + j0 + jx + v];
            sbb_[v] = g_sbb[r * NT + j0 + jx + v];
        }
        const float invH = 1.0f / (float)HD;
#pragma unroll
        for (int u = 0; u < 4; u++)
#pragma unroll
            for (int v = 0; v < 4; v++) {
                float mu  = (sa_[u] + sb_[v]) * invH;
                float e2  = (saa_[u] + sbb_[v] + 2.0f * cross[u][v]) * invH;
                float var = e2 - mu * mu;
                float rstd = rsqrtf(var + 1e-5f);
                q[u][v] = rstd;
                m[u][v] = mu * rstd;
            }
    }

    // ---- phase 2: s = sum_h relu((p - mu)*rstd*gamma + beta) * w2 ----
    float s[4][4];
#pragma unroll
    for (int u = 0; u < 4; u++)
#pragma unroll
        for (int v = 0; v < 4; v++) s[u][v] = 0.f;

    for (int k0 = 0; k0 < HD; k0 += 32) {
#pragma unroll
        for (int p = 0; p < 2; p++) {
            int id = t + p * 256;
            int rw = id >> 3, c4 = (id & 7) * 4;
            float4 av = *(const float4*)&Ab[(size_t)rw * HD + k0 + c4];
            float4 bv = *(const float4*)&Bb[(size_t)rw * HD + k0 + c4];
            As[rw][c4 + 0] = av.x; As[rw][c4 + 1] = av.y;
            As[rw][c4 + 2] = av.z; As[rw][c4 + 3] = av.w;
            Bs[rw][c4 + 0] = bv.x; Bs[rw][c4 + 1] = bv.y;
            Bs[rw][c4 + 2] = bv.z; Bs[rw][c4 + 3] = bv.w;
        }
        if (t < 32) {
            gs [t] = gamma[r * HD + k0 + t];
            bes[t] = beta [r * HD + k0 + t];
            ws [t] = w2   [r * HD + k0 + t];
        }
        __syncthreads();
#pragma unroll
        for (int k = 0; k < 32; k++) {
            float g = gs[k], be = bes[k], w = ws[k];
            float a[4], b[4];
#pragma unroll
            for (int u = 0; u < 4; u++) a[u] = As[iy + u][k];
#pragma unroll
            for (int v = 0; v < 4; v++) b[v] = Bs[jx + v][k];
#pragma unroll
            for (int u = 0; u < 4; u++)
#pragma unroll
                for (int v = 0; v < 4; v++) {
                    float pz = a[u] + b[v];
                    float z  = fmaf(pz, q[u][v], -m[u][v]);   // (p - mu)*rstd
                    float tv = fmaf(z, g, be);
                    tv = fmaxf(tv, 0.0f);
                    s[u][v] = fmaf(tv, w, s[u][v]);
                }
        }
        __syncthreads();
    }

    const float bb = b2[r];
    float* __restrict__ Sout = g_S + (size_t)r * NT * NT;
#pragma unroll
    for (int u = 0; u < 4; u++) {
        float4 o;
        o.x = s[u][0] + bb;
        o.y = s[u][1] + bb;
        o.z = s[u][2] + bb;
        o.w = s[u][3] + bb;
        *(float4*)&Sout[(size_t)(i0 + iy + u) * NT + j0 + jx] = o;
    }
}

// ---------------- 5) finalize: max/argmax over r, threshold mask ----------------
// out layout: [x (262144)][best_score (262144)][best_rel (262144)][edge_mask (262144)]
__global__ void finalize_kernel(float* __restrict__ out) {
    int idx = blockIdx.x * blockDim.x + threadIdx.x;   // 262144
    float s0 = g_S[idx];
    float s1 = g_S[NT * NT + idx];
    float s2 = g_S[2 * NT * NT + idx];
    float s3 = g_S[3 * NT * NT + idx];
    float best = s0; int rel = 0;
    if (s1 > best) { best = s1; rel = 1; }
    if (s2 > best) { best = s2; rel = 2; }
    if (s3 > best) { best = s3; rel = 3; }
    int i = idx >> 9, j = idx & (NT - 1);
    out[NT * NT     + idx] = best;
    out[2 * NT * NT + idx] = (float)rel;
    out[3 * NT * NT + idx] = (i != j && best > 0.2f) ? 1.0f : 0.0f;
}

// ---------------- launch ----------------
extern "C" void kernel_launch(void* const* d_in, const int* in_sizes, int n_in,
                              void* d_out, int out_size) {
    (void)in_sizes; (void)n_in; (void)out_size;
    const float* img   = (const float*)d_in[0];
    const float* txt   = (const float*)d_in[1];
    const float* W1    = (const float*)d_in[2];
    const float* b1    = (const float*)d_in[3];
    const float* gamma = (const float*)d_in[4];
    const float* beta  = (const float*)d_in[5];
    const float* w2    = (const float*)d_in[6];
    const float* b2    = (const float*)d_in[7];
    float* out = (float*)d_out;

    concat_kernel<<<256, 256>>>((const float4*)img, (const float4*)txt, (float4*)out);

    dim3 gg(8, 8, 8);                 // (h tiles, i tiles, r*2+half)
    gemm_kernel<<<gg, 256>>>(W1, b1);

    rowstats_kernel<<<512, 256>>>();

    dim3 pg(8, 8, 4);                 // (j tiles, i tiles, r)
    pair_kernel<<<pg, 256>>>(gamma, beta, w2, b2);

    finalize_kernel<<<1024, 256>>>(out);
}